// round 16
// baseline (speedup 1.0000x reference)
#include <cuda_runtime.h>
#include <cstdint>

// Problem constants: B=8, N=500000, H=W=512, HALF_CENTOR=true
#define BB    8
#define NPTS  500000
#define HH    512
#define WW    512
#define HW    (HH * WW)          // 262,144 cells per batch
#define NCELL (BB * HW)          // 2,097,152 cells

#define T         256
#define SCAT_BPB  ((NPTS + T - 1) / T)   // 1954 scatter blocks per batch
#define FIN_BPB   ((HW / 4) / T)         // 256 finalize blocks per batch
#define GPB       (HW / 4)               // uint4 groups per batch

// Separate scratch arrays; zero sentinel (module-load zero init); finalize
// restores zeros after reading -> every call / graph replay starts clean.
__device__ unsigned int g_min[NCELL];      // 8 MB: max of ~enc_f(cost), 0 = empty
__device__ unsigned int g_cnt[NCELL];      // 8 MB: count, 0 = empty
__device__ unsigned int g_done[BB];        // scatter blocks retired per batch
__device__ unsigned int g_fin_done[BB];    // finalize blocks retired per batch

// Order-preserving float -> uint (monotone increasing).
__device__ __forceinline__ unsigned int enc_f(float f) {
    unsigned int u = __float_as_uint(f);
    return (u & 0x80000000u) ? ~u : (u | 0x80000000u);
}
__device__ __forceinline__ float dec_f(unsigned int u) {
    return __uint_as_float((u & 0x80000000u) ? (u & 0x7FFFFFFFu) : ~u);
}

__device__ __forceinline__ unsigned int ld_acq(const unsigned int* p) {
    unsigned int v;
    asm volatile("ld.acquire.gpu.b32 %0, [%1];" : "=r"(v) : "l"(p) : "memory");
    return v;
}

// ---------------------------------------------------------------------------
// Single fused launch. Blocks [0, BB*SCAT_BPB): scatter (never waits, full
// atomic-queue depth, exact round-7 inner loop). Blocks after that: finalize,
// gated per batch on the scatter-block counter. Finalize(b) overlaps
// scatter(b+1..): it consumes issue/DRAM slots the atomic-bound scatter
// leaves idle (round-13 mix evidence: overlap is ~free).
// ---------------------------------------------------------------------------
__global__ void k_fused(const float2* __restrict__ points,   // [B*N] (x,y)
                        const float*  __restrict__ costs,    // [B*N]
                        float* __restrict__ out_cost,
                        float* __restrict__ out_mask,
                        const float* __restrict__ default_cost) {
    int bid = blockIdx.x;
    if (bid < BB * SCAT_BPB) {
        // ---------------- scatter ----------------
        int b = bid / SCAT_BPB;
        int t = (bid - b * SCAT_BPB) * T + threadIdx.x;
        if (t < NPTS) {
            int gi = b * NPTS + t;
            float2 p = points[gi];
            int ix = (int)floorf(p.x + 0.5f);
            int iy = (int)floorf(p.y + 0.5f);
            if ((unsigned)ix < (unsigned)WW && (unsigned)iy < (unsigned)HH) {
                int cell = b * HW + iy * WW + ix;
                float c = costs[gi];
                atomicMax(&g_min[cell], ~enc_f(c));  // RED (result unused)
                atomicAdd(&g_cnt[cell], 1u);         // RED
            }
        }
        // publish completion: REDs ordered before the counter bump
        __threadfence();
        __syncthreads();
        if (threadIdx.x == 0)
            atomicAdd(&g_done[bid / SCAT_BPB], 1u);
    } else {
        // ---------------- finalize ----------------
        int f = bid - BB * SCAT_BPB;
        int b = f / FIN_BPB;
        int g = b * GPB + (f - b * FIN_BPB) * T + threadIdx.x;

        // gate: wait until all scatter blocks of batch b retired
        if (threadIdx.x == 0) {
            while (ld_acq(&g_done[b]) < (unsigned)SCAT_BPB)
                __nanosleep(200);
        }
        __syncthreads();
        __threadfence();

        uint4 m = reinterpret_cast<const uint4*>(g_min)[g];
        uint4 c = reinterpret_cast<const uint4*>(g_cnt)[g];

        float d = __ldg(default_cost);
        float4 cost;
        cost.x = c.x ? dec_f(~m.x) : d;
        cost.y = c.y ? dec_f(~m.y) : d;
        cost.z = c.z ? dec_f(~m.z) : d;
        cost.w = c.w ? dec_f(~m.w) : d;
        __stcs(&reinterpret_cast<float4*>(out_cost)[g], cost);

        if (out_mask) {
            float4 mk = make_float4((float)((int)c.x - 1), (float)((int)c.y - 1),
                                    (float)((int)c.z - 1), (float)((int)c.w - 1));
            __stcs(&reinterpret_cast<float4*>(out_mask)[g], mk);
        }

        // restore zero sentinels (plain stores: keep L2-resident)
        uint4 z = make_uint4(0u, 0u, 0u, 0u);
        reinterpret_cast<uint4*>(g_min)[g] = z;
        reinterpret_cast<uint4*>(g_cnt)[g] = z;

        // reset counters for the next replay: last finalize block of batch b
        __syncthreads();
        if (threadIdx.x == 0) {
            unsigned int r = atomicAdd(&g_fin_done[b], 1u);
            if (r == FIN_BPB - 1) {          // all gates of batch b passed
                g_done[b] = 0u;
                g_fin_done[b] = 0u;
                __threadfence();
            }
        }
    }
}

// ---------------------------------------------------------------------------
// Launcher. Inputs: points[B,N,2] f32, costs[B,N] f32, default_cost f32,
// height i32, width i32. Output: [cost | mask] as f32.
// ---------------------------------------------------------------------------
extern "C" void kernel_launch(void* const* d_in, const int* in_sizes, int n_in,
                              void* d_out, int out_size) {
    const float2* points       = (const float2*)d_in[0];
    const float*  costs        = (const float*)d_in[1];
    const float*  default_cost = (const float*)d_in[2];

    float* out_cost = (float*)d_out;
    float* out_mask = (out_size >= 2 * NCELL) ? out_cost + NCELL : nullptr;

    k_fused<<<BB * SCAT_BPB + BB * FIN_BPB, T>>>(points, costs,
                                                 out_cost, out_mask,
                                                 default_cost);
}

// round 17
// speedup vs baseline: 1.7493x; 1.7493x over previous
#include <cuda_runtime.h>
#include <cstdint>

// Problem constants: B=8, N=500000, H=W=512, HALF_CENTOR=true
#define BB    8
#define NPTS  500000
#define HH    512
#define WW    512
#define NCELL (BB * HH * WW)   // 2,097,152 cells

// Separate scratch arrays (interleaved (min,cnt) serialized in one LTS atomic
// bank — round-2 evidence). Zero is the sentinel for both (module-load zero
// init); k_final restores zeros after reading, so every kernel_launch call /
// graph replay sees zeros on entry.
//   g_min[cell] = max over points of mkey = ~enc_f(cost); larger mkey ==
//                 smaller cost, every float encodes to mkey >= 1.
//   g_cnt[cell] = number of points that hit the cell.
__device__ unsigned int g_min[NCELL];   // 8 MB
__device__ unsigned int g_cnt[NCELL];   // 8 MB

// Order-preserving float -> uint (monotone increasing).
__device__ __forceinline__ unsigned int enc_f(float f) {
    unsigned int u = __float_as_uint(f);
    return (u & 0x80000000u) ? ~u : (u | 0x80000000u);
}
__device__ __forceinline__ float dec_f(unsigned int u) {
    return __uint_as_float((u & 0x80000000u) ? (u & 0x7FFFFFFFu) : ~u);
}

// ---------------------------------------------------------------------------
// Scatter: 1 point per thread, UNCONDITIONAL fire-and-forget REDs (proven
// round-7 body, untouched). After issuing its REDs each thread signals PDL
// launch-readiness — a cheap griddepcontrol hint, NO memory drain (the
// drain-per-block __threadfence was what sank the round-16 fusion).
// ---------------------------------------------------------------------------
__global__ void k_scatter(const float2* __restrict__ points,  // [B*N] (x,y)
                          const float*  __restrict__ costs) { // [B*N]
    int n = blockIdx.x * blockDim.x + threadIdx.x;
    int b = blockIdx.y;
    if (n < NPTS) {
        int gi = b * NPTS + n;
        float2 p = points[gi];
        int ix = (int)floorf(p.x + 0.5f);
        int iy = (int)floorf(p.y + 0.5f);
        if ((unsigned)ix < (unsigned)WW && (unsigned)iy < (unsigned)HH) {
            int cell = (b * HH + iy) * WW + ix;
            float c = costs[gi];
            atomicMax(&g_min[cell], ~enc_f(c));  // RED (result unused)
            atomicAdd(&g_cnt[cell], 1u);         // RED
        }
    }
    // allow the dependent k_final grid to begin launching/ramping now;
    // it still waits (gridDependencySynchronize) for our full completion
    // before it reads the scratch arrays.
    cudaTriggerProgrammaticLaunchCompletion();
}

// ---------------------------------------------------------------------------
// Finalize: 4 cells per thread (proven 9.4us shape). Launched with PDL so it
// ramps under the scatter tail: prologue (indices + default_cost load — an
// INPUT, independent of scatter) runs first, then the grid-dependency wait,
// then the scratch reads.
// ---------------------------------------------------------------------------
__global__ void k_final(float* __restrict__ out_cost,
                        float* __restrict__ out_mask,
                        const float* __restrict__ default_cost) {
    int i = blockIdx.x * blockDim.x + threadIdx.x;   // group of 4 cells
    float d = __ldg(default_cost);                    // safe pre-sync (input)

    // wait for k_scatter's grid to complete (all REDs visible)
    cudaGridDependencySynchronize();

    if (i >= NCELL / 4) return;
    uint4 m = reinterpret_cast<const uint4*>(g_min)[i];
    uint4 c = reinterpret_cast<const uint4*>(g_cnt)[i];

    float4 cost;
    cost.x = c.x ? dec_f(~m.x) : d;
    cost.y = c.y ? dec_f(~m.y) : d;
    cost.z = c.z ? dec_f(~m.z) : d;
    cost.w = c.w ? dec_f(~m.w) : d;
    reinterpret_cast<float4*>(out_cost)[i] = cost;

    if (out_mask) {
        float4 mk = make_float4((float)((int)c.x - 1), (float)((int)c.y - 1),
                                (float)((int)c.z - 1), (float)((int)c.w - 1));
        reinterpret_cast<float4*>(out_mask)[i] = mk;
    }

    // restore zero sentinels (L2-resident stores; next call starts clean)
    uint4 z = make_uint4(0u, 0u, 0u, 0u);
    reinterpret_cast<uint4*>(g_min)[i] = z;
    reinterpret_cast<uint4*>(g_cnt)[i] = z;
}

// ---------------------------------------------------------------------------
// Launcher. Inputs: points[B,N,2] f32, costs[B,N] f32, default_cost f32,
// height i32, width i32. Output: [cost | mask] as f32.
// k_final is launched with ProgrammaticStreamSerialization (PDL): it begins
// launching as soon as k_scatter triggers, overlapping ramp with the scatter
// tail while the in-kernel sync preserves the data dependency.
// ---------------------------------------------------------------------------
extern "C" void kernel_launch(void* const* d_in, const int* in_sizes, int n_in,
                              void* d_out, int out_size) {
    const float2* points       = (const float2*)d_in[0];
    const float*  costs        = (const float*)d_in[1];
    const float*  default_cost = (const float*)d_in[2];

    float* out_cost = (float*)d_out;
    float* out_mask = (out_size >= 2 * NCELL) ? out_cost + NCELL : nullptr;

    const int T = 256;
    dim3 sg((NPTS + T - 1) / T, BB);
    k_scatter<<<sg, T>>>(points, costs);

    cudaLaunchConfig_t cfg = {};
    cfg.gridDim  = dim3((NCELL / 4 + T - 1) / T, 1, 1);
    cfg.blockDim = dim3(T, 1, 1);
    cfg.dynamicSmemBytes = 0;
    cfg.stream = 0;   // same (capture) stream as k_scatter
    cudaLaunchAttribute attrs[1];
    attrs[0].id = cudaLaunchAttributeProgrammaticStreamSerialization;
    attrs[0].val.programmaticStreamSerializationAllowed = 1;
    cfg.attrs = attrs;
    cfg.numAttrs = 1;
    cudaLaunchKernelEx(&cfg, k_final, out_cost, out_mask, default_cost);
}